// round 13
// baseline (speedup 1.0000x reference)
#include <cuda_runtime.h>
#include <cuda_bf16.h>
#include <cstdint>

// MultiHeadDenseSynthesizer: B=64, L=500, F=256, H=4, dk=64
// Round 13: k_proj restructured to full-N (all 4 heads per CTA, M=64,
// cp.async double-buffered weight chunks) -> 4x less A traffic.
// attn/final unchanged from round 12.

#define BB  64
#define LL  500
#define FF  256
#define HH  4
#define DKK 64
#define BLL (BB*LL)
#define BH  (BB*HH)
#define LPAD 512

// ---------------- device scratch (zero-initialized at load) ----------------
__device__ __nv_bfloat16 g_ctxb[BLL*FF];   // attn out, bf16, [b*L+l][f]
__device__ uint4 g_wt_h4[BH*LL*DKK/8];     // W  [bh][l][d] bf16
__device__ uint4 g_vT_h4[BH*DKK*LPAD/8];   // Vt [bh][d][j] bf16
__device__ uint4 g_w2T_h4[LPAD*DKK/8];     // w2T [j][d] bf16
__device__ uint4 g_wqsT4h[FF*FF/8];        // [n][k] bf16
__device__ uint4 g_wvsT4h[FF*FF/8];
__device__ uint4 g_fcwT4h[FF*FF/8];
__device__ uint4 g_w1T4h[DKK*DKK/8];

__device__ __forceinline__ uint32_t pack_hi2(float x, float y) {
    __nv_bfloat162 t = __float22bfloat162_rn(make_float2(x, y));
    return *(uint32_t*)&t;
}
__device__ __forceinline__ void mma16816(float c[4], const uint32_t a[4], const uint32_t b[2]) {
    asm volatile(
        "mma.sync.aligned.m16n8k16.row.col.f32.bf16.bf16.f32 "
        "{%0,%1,%2,%3}, {%4,%5,%6,%7}, {%8,%9}, {%0,%1,%2,%3};"
        : "+f"(c[0]), "+f"(c[1]), "+f"(c[2]), "+f"(c[3])
        : "r"(a[0]), "r"(a[1]), "r"(a[2]), "r"(a[3]), "r"(b[0]), "r"(b[1]));
}
__device__ __forceinline__ void cpa16(uint32_t s, const void* g) {
    asm volatile("cp.async.cg.shared.global [%0], [%1], 16;" :: "r"(s), "l"(g));
}
#define CPA_COMMIT() asm volatile("cp.async.commit_group;" ::: "memory")
#define CPA_WAIT0()  asm volatile("cp.async.wait_group 0;"  ::: "memory")

// ---------------------------------------------------------------------------
// k_prep_all: all weight transposes -> bf16.
// ---------------------------------------------------------------------------
__global__ void k_prep_all(const float* __restrict__ w2, const float* __restrict__ wqs,
                           const float* __restrict__ wvs, const float* __restrict__ fcw,
                           const float* __restrict__ w1)
{
    int bx = blockIdx.x, tid = threadIdx.x;
    float v; __nv_bfloat16* dh; int idx;
    if (bx < 128) {
        idx = bx*256 + tid;                       // j*64 + d
        int j = idx >> 6, d = idx & 63;
        v = (j < LL) ? w2[d*LL + j] : 0.f;
        dh = (__nv_bfloat16*)g_w2T_h4;
    } else if (bx < 384) {
        idx = (bx - 128)*256 + tid;               // n*256 + k
        int n = idx >> 8, k = idx & 255;
        v = wqs[k*FF + n];
        dh = (__nv_bfloat16*)g_wqsT4h;
    } else if (bx < 640) {
        idx = (bx - 384)*256 + tid;
        int n = idx >> 8, k = idx & 255;
        v = wvs[k*FF + n];
        dh = (__nv_bfloat16*)g_wvsT4h;
    } else if (bx < 896) {
        idx = (bx - 640)*256 + tid;
        int n = idx >> 8, k = idx & 255;
        v = fcw[k*FF + n];
        dh = (__nv_bfloat16*)g_fcwT4h;
    } else {
        idx = (bx - 896)*256 + tid;               // n*64 + k
        int n = idx >> 6, k = idx & 63;
        v = w1[k*DKK + n];
        dh = (__nv_bfloat16*)g_w1T4h;
    }
    dh[idx] = __float2bfloat16(v);
}

// ---------------------------------------------------------------------------
// Kernel 1: projections, full-N. grid (500, 2), 256 thr.
// M=64/CTA; 8 warps = 4 row-groups x 2 col-halves (128 cols = 2 heads each).
// Weight [n][k] staged in k-chunks of 64, cp.async double-buffered.
// mode 0 (blockIdx.y=0): qh over all heads, then per-head w1 GEMM -> g_wt.
// mode 1: vh, transpose via smem -> g_vT.
// ---------------------------------------------------------------------------
#define PJ_FTILE (256*144)               // 36864 per buffer
#define PJ_W1OFF (2*PJ_FTILE)            // 73728
#define PJ_B1OFF (PJ_W1OFF + 64*144)     // 82944
#define PJ_SMEM  (PJ_B1OFF + 256)        // 83200

__global__ void __launch_bounds__(256)
k_proj_mma(const float* __restrict__ qin, const float* __restrict__ vin,
           const float* __restrict__ b1)
{
    extern __shared__ char smem[];
    char* sW1h = smem + PJ_W1OFF;
    float* b1s = (float*)(smem + PJ_B1OFF);
    float* vtr = (float*)smem;           // mode1 epilogue alias: [256 cols][68]
    const uint32_t sWa = (uint32_t)__cvta_generic_to_shared(smem);

    const int tid  = threadIdx.x;
    const int lane = tid & 31, wid = tid >> 5;
    const int g4 = lane >> 2, t4 = lane & 3;
    const int half = wid >> 2, wrow = wid & 3;
    const int ncol0 = half * 128;
    const int m0 = blockIdx.x * 64;
    const int mode = blockIdx.y;
    const float* A = mode ? vin : qin;
    const uint4* WTh = mode ? g_wvsT4h : g_wqsT4h;

    const int r0 = wrow*16 + g4;
    const int gr0 = m0 + r0, gr1 = gr0 + 8;

    if (!mode) {
        for (int idx = tid; idx < 512; idx += 256) {
            int row = idx >> 3, gq = idx & 7;
            *(uint4*)(sW1h + row*144 + gq*16) = g_w1T4h[row*8 + gq];
        }
        if (tid < 64) b1s[tid] = b1[tid];
    }

    float sacc[16][4];
#pragma unroll
    for (int nt = 0; nt < 16; nt++)
#pragma unroll
        for (int e = 0; e < 4; e++) sacc[nt][e] = 0.f;

    // stage kc=0 into buffer 0
#pragma unroll
    for (int it = 0; it < 8; it++) {
        int idx = tid + it*256;
        int row = idx >> 3, gq = idx & 7;
        cpa16(sWa + row*144 + gq*16, &WTh[row*32 + gq]);
    }
    CPA_COMMIT();

    for (int kc = 0; kc < 4; kc++) {
        const int buf = kc & 1;
        CPA_WAIT0();
        __syncthreads();
        if (kc < 3) {
            const uint32_t dW = sWa + (buf ^ 1)*PJ_FTILE;
#pragma unroll
            for (int it = 0; it < 8; it++) {
                int idx = tid + it*256;
                int row = idx >> 3, gq = idx & 7;
                cpa16(dW + row*144 + gq*16, &WTh[row*32 + (kc+1)*8 + gq]);
            }
            CPA_COMMIT();
        }
        const char* sWh = smem + buf*PJ_FTILE;

#pragma unroll
        for (int kt = 0; kt < 4; kt++) {
            int cg = kc*64 + kt*16 + t4*2;
            uint32_t ah[4];
            float2 f;
            f = *(const float2*)(A + (size_t)gr0*FF + cg);     ah[0] = pack_hi2(f.x, f.y);
            f = *(const float2*)(A + (size_t)gr1*FF + cg);     ah[1] = pack_hi2(f.x, f.y);
            f = *(const float2*)(A + (size_t)gr0*FF + cg + 8); ah[2] = pack_hi2(f.x, f.y);
            f = *(const float2*)(A + (size_t)gr1*FF + cg + 8); ah[3] = pack_hi2(f.x, f.y);
            int koff = (kt*16 + t4*2)*2;
#pragma unroll
            for (int nt = 0; nt < 16; nt++) {
                int off = (ncol0 + nt*8 + g4)*144 + koff;
                uint32_t bh2[2];
                bh2[0] = *(const uint32_t*)(sWh + off);
                bh2[1] = *(const uint32_t*)(sWh + off + 16);
                mma16816(sacc[nt], ah, bh2);
            }
        }
    }

    if (mode) {
        // ---- transpose vh via smem -> g_vT [bh][d][j] bf16
        __syncthreads();   // MMA reads of buffers done; reuse as vtr
#pragma unroll
        for (int nt = 0; nt < 16; nt++) {
            int c = ncol0 + nt*8 + t4*2;
            vtr[c*68 + r0]           = sacc[nt][0];
            vtr[(c+1)*68 + r0]       = sacc[nt][1];
            vtr[c*68 + r0 + 8]       = sacc[nt][2];
            vtr[(c+1)*68 + r0 + 8]   = sacc[nt][3];
        }
        __syncthreads();
        __nv_bfloat16* vTh = (__nv_bfloat16*)g_vT_h4;
        for (int idx = tid; idx < 256*32; idx += 256) {
            int c = idx >> 5, jp = idx & 31;
            int gj = m0 + 2*jp;
            int b = gj / LL, p = gj - b*LL;   // pairs never cross batch
            int head = c >> 6, d = c & 63;
            size_t a = ((size_t)((b*HH + head)*DKK + d))*LPAD + p;
            *(uint32_t*)(vTh + a) = pack_hi2(vtr[c*68 + 2*jp], vtr[c*68 + 2*jp + 1]);
        }
        return;
    }

    // ---- mode 0: per-head w1 GEMM via C-frag -> A-frag hand-off
    __nv_bfloat16* wth = (__nv_bfloat16*)g_wt_h4;
    int b0_ = gr0 / LL, l0_ = gr0 - b0_*LL;
    int b1_ = gr1 / LL, l1_ = gr1 - b1_*LL;

#pragma unroll
    for (int hb = 0; hb < 2; hb++) {
        const int head = half*2 + hb;
        uint32_t ph[4][4];
#pragma unroll
        for (int nt = 0; nt < 8; nt++) {
            int kt = nt >> 1, i0 = (nt & 1) * 2;
            ph[kt][i0]     = pack_hi2(sacc[hb*8 + nt][0], sacc[hb*8 + nt][1]);
            ph[kt][i0 + 1] = pack_hi2(sacc[hb*8 + nt][2], sacc[hb*8 + nt][3]);
        }

        float s2[8][4];
#pragma unroll
        for (int nt = 0; nt < 8; nt++) {
            int col = nt*8 + t4*2;
            s2[nt][0] = s2[nt][2] = b1s[col];
            s2[nt][1] = s2[nt][3] = b1s[col + 1];
        }
#pragma unroll
        for (int kt = 0; kt < 4; kt++) {
#pragma unroll
            for (int nt = 0; nt < 8; nt++) {
                int off = (nt*8 + g4)*144 + (kt*16 + t4*2)*2;
                uint32_t bh2[2];
                bh2[0] = *(const uint32_t*)(sW1h + off);
                bh2[1] = *(const uint32_t*)(sW1h + off + 16);
                mma16816(s2[nt], ph[kt], bh2);
            }
        }

        size_t base0 = ((size_t)((b0_*HH + head)*LL + l0_))*DKK;
        size_t base1 = ((size_t)((b1_*HH + head)*LL + l1_))*DKK;
#pragma unroll
        for (int nt = 0; nt < 8; nt++) {
            int d = nt*8 + t4*2;
            *(uint32_t*)(wth + base0 + d) =
                pack_hi2(fmaxf(s2[nt][0], 0.f), fmaxf(s2[nt][1], 0.f));
            *(uint32_t*)(wth + base1 + d) =
                pack_hi2(fmaxf(s2[nt][2], 0.f), fmaxf(s2[nt][3], 0.f));
        }
    }
}

// ---------------------------------------------------------------------------
// Kernel 2: attention, cp.async double-buffered. grid (4, H, B), 256 thr.
// ---------------------------------------------------------------------------
#define SPITCH 144
#define ATILE (64*SPITCH)   // 9216

__global__ void __launch_bounds__(256)
k_attn_mma(const float* __restrict__ b2)
{
    __shared__ float b2all[512];
    __shared__ __align__(16) char sW2[2][ATILE];
    __shared__ __align__(16) char sV [2][ATILE];

    const int tid  = threadIdx.x;
    const int lane = tid & 31, wid = tid >> 5;
    const int g4 = lane >> 2, t4 = lane & 3;
    const int l0 = blockIdx.x * 128;
    const int h  = blockIdx.y, b = blockIdx.z;
    const int bh = b*HH + h;
    const int r0 = l0 + wid*16 + g4;

    const uint32_t sW2a = (uint32_t)__cvta_generic_to_shared(sW2);
    const uint32_t sVa  = (uint32_t)__cvta_generic_to_shared(sV);

#pragma unroll
    for (int it = 0; it < 2; it++) {
        int i = tid + it*256;
        b2all[i] = (i < LL) ? b2[i] : 0.f;
    }

    const __nv_bfloat16* wth = (const __nv_bfloat16*)g_wt_h4;
    uint32_t aWh[4][4];
    {
        const bool v0 = (r0 < LL), v1 = (r0 + 8 < LL);
        size_t base0 = (size_t)(bh*LL + r0)*DKK;
        size_t base1 = (size_t)(bh*LL + r0 + 8)*DKK;
#pragma unroll
        for (int kt = 0; kt < 4; kt++) {
            int c0 = kt*16 + t4*2, c8 = c0 + 8;
            aWh[kt][0] = v0 ? *(const uint32_t*)(wth + base0 + c0) : 0u;
            aWh[kt][1] = v1 ? *(const uint32_t*)(wth + base1 + c0) : 0u;
            aWh[kt][2] = v0 ? *(const uint32_t*)(wth + base0 + c8) : 0u;
            aWh[kt][3] = v1 ? *(const uint32_t*)(wth + base1 + c8) : 0u;
        }
    }

    float oacc[8][4];
#pragma unroll
    for (int nt = 0; nt < 8; nt++)
#pragma unroll
        for (int e = 0; e < 4; e++) oacc[nt][e] = 0.f;
    float dp0 = 0.f, dp1 = 0.f;

#pragma unroll
    for (int it = 0; it < 2; it++) {
        int idx = tid + it*256;
        int rr = idx >> 3, gg = idx & 7;
        cpa16(sW2a + rr*SPITCH + gg*16, &g_w2T_h4[(size_t)rr*8 + gg]);
        cpa16(sVa  + rr*SPITCH + gg*16,
              &g_vT_h4[(size_t)(bh*DKK + rr)*(LPAD/8) + gg]);
    }
    CPA_COMMIT();

    for (int c = 0; c < 8; c++) {
        const int j0 = c * 64;
        const int buf = c & 1;
        CPA_WAIT0();
        __syncthreads();
        if (c < 7) {
            const int jn = (c + 1) * 64;
            const uint32_t dW2 = sW2a + (buf ^ 1)*ATILE;
            const uint32_t dV  = sVa  + (buf ^ 1)*ATILE;
#pragma unroll
            for (int it = 0; it < 2; it++) {
                int idx = tid + it*256;
                int rr = idx >> 3, gg = idx & 7;
                cpa16(dW2 + rr*SPITCH + gg*16, &g_w2T_h4[(size_t)(jn + rr)*8 + gg]);
                cpa16(dV  + rr*SPITCH + gg*16,
                      &g_vT_h4[(size_t)(bh*DKK + rr)*(LPAD/8) + (jn >> 3) + gg]);
            }
            CPA_COMMIT();
        }

        const char* w2b = sW2[buf];
        const char* vb  = sV[buf];

        float sacc[8][4];
#pragma unroll
        for (int nt = 0; nt < 8; nt++)
#pragma unroll
            for (int e = 0; e < 4; e++) sacc[nt][e] = 0.f;

#pragma unroll
        for (int kt = 0; kt < 4; kt++) {
#pragma unroll
            for (int nt = 0; nt < 8; nt++) {
                int off = (nt*8 + g4)*SPITCH + (kt*16 + t4*2)*2;
                uint32_t bh2[2];
                bh2[0] = *(const uint32_t*)(w2b + off);
                bh2[1] = *(const uint32_t*)(w2b + off + 16);
                mma16816(sacc[nt], aWh[kt], bh2);
            }
        }

        uint32_t phA[4][4];
#pragma unroll
        for (int nt = 0; nt < 8; nt++) {
            int jl = nt*8 + t4*2;
            int jg = j0 + jl;
            float bb0 = b2all[jg], bb1 = b2all[jg + 1];
            float p0 = (jg     < LL) ? __expf(sacc[nt][0] + bb0) : 0.f;
            float p1 = (jg + 1 < LL) ? __expf(sacc[nt][1] + bb1) : 0.f;
            float p2 = (jg     < LL) ? __expf(sacc[nt][2] + bb0) : 0.f;
            float p3 = (jg + 1 < LL) ? __expf(sacc[nt][3] + bb1) : 0.f;
            dp0 += p0 + p1;
            dp1 += p2 + p3;
            int kt = nt >> 1, i0 = (nt & 1) * 2;
            phA[kt][i0]     = pack_hi2(p0, p1);
            phA[kt][i0 + 1] = pack_hi2(p2, p3);
        }

#pragma unroll
        for (int kt = 0; kt < 4; kt++) {
#pragma unroll
            for (int nt = 0; nt < 8; nt++) {
                int off = (nt*8 + g4)*SPITCH + (kt*16 + t4*2)*2;
                uint32_t bvh[2];
                bvh[0] = *(const uint32_t*)(vb + off);
                bvh[1] = *(const uint32_t*)(vb + off + 16);
                mma16816(oacc[nt], phA[kt], bvh);
            }
        }
    }

    dp0 += __shfl_xor_sync(0xffffffffu, dp0, 1);
    dp0 += __shfl_xor_sync(0xffffffffu, dp0, 2);
    dp1 += __shfl_xor_sync(0xffffffffu, dp1, 1);
    dp1 += __shfl_xor_sync(0xffffffffu, dp1, 2);
    float inv0 = 1.f / dp0, inv1 = 1.f / dp1;

    if (r0 < LL) {
        __nv_bfloat16* dst = g_ctxb + ((size_t)(b*LL + r0))*FF + h*DKK + t4*2;
#pragma unroll
        for (int nt = 0; nt < 8; nt++)
            *(uint32_t*)(dst + nt*8) = pack_hi2(oacc[nt][0]*inv0, oacc[nt][1]*inv0);
    }
    if (r0 + 8 < LL) {
        __nv_bfloat16* dst = g_ctxb + ((size_t)(b*LL + r0 + 8))*FF + h*DKK + t4*2;
#pragma unroll
        for (int nt = 0; nt < 8; nt++)
            *(uint32_t*)(dst + nt*8) = pack_hi2(oacc[nt][2]*inv1, oacc[nt][3]*inv1);
    }
}

// ---------------------------------------------------------------------------
// Kernel 3: out = LN(ctx @ fcwT^T + q). grid 500 (M=64/CTA), 256 thr.
// ---------------------------------------------------------------------------
#define FTILE (256*144)          // 36864
#define FN_SMEM (2*FTILE)        // 73728

__global__ void __launch_bounds__(256)
k_final_mma(const float* __restrict__ qin, const float* __restrict__ lng,
            const float* __restrict__ lnb, float* __restrict__ out)
{
    extern __shared__ char smem[];
    __shared__ float red_s[64][2], red_q[64][2];
    const uint32_t sFa = (uint32_t)__cvta_generic_to_shared(smem);

    const int tid  = threadIdx.x;
    const int lane = tid & 31, wid = tid >> 5;
    const int g4 = lane >> 2, t4 = lane & 3;
    const int half = wid >> 2, wrow = wid & 3;
    const int ncol0 = half * 128;
    const int m0 = blockIdx.x * 64;
    const int r0 = wrow*16 + g4;
    const int gr0 = m0 + r0, gr1 = gr0 + 8;
    const __nv_bfloat16* ctxb = g_ctxb;

    float sacc[16][4];
#pragma unroll
    for (int nt = 0; nt < 16; nt++)
#pragma unroll
        for (int e = 0; e < 4; e++) sacc[nt][e] = 0.f;

#pragma unroll
    for (int it = 0; it < 8; it++) {
        int idx = tid + it*256;
        int row = idx >> 3, gq = idx & 7;
        cpa16(sFa + row*144 + gq*16, &g_fcwT4h[row*32 + gq]);
    }
    CPA_COMMIT();

    for (int kc = 0; kc < 4; kc++) {
        const int buf = kc & 1;
        CPA_WAIT0();
        __syncthreads();
        if (kc < 3) {
            const uint32_t dF = sFa + (buf ^ 1)*FTILE;
#pragma unroll
            for (int it = 0; it < 8; it++) {
                int idx = tid + it*256;
                int row = idx >> 3, gq = idx & 7;
                cpa16(dF + row*144 + gq*16, &g_fcwT4h[row*32 + (kc+1)*8 + gq]);
            }
            CPA_COMMIT();
        }
        const char* sFh = smem + buf*FTILE;

#pragma unroll
        for (int kt = 0; kt < 4; kt++) {
            int cg = kc*64 + kt*16 + t4*2;
            uint32_t ah[4];
            ah[0] = *(const uint32_t*)(ctxb + (size_t)gr0*FF + cg);
            ah[1] = *(const uint32_t*)(ctxb + (size_t)gr1*FF + cg);
            ah[2] = *(const uint32_t*)(ctxb + (size_t)gr0*FF + cg + 8);
            ah[3] = *(const uint32_t*)(ctxb + (size_t)gr1*FF + cg + 8);
            int koff = (kt*16 + t4*2)*2;
#pragma unroll
            for (int nt = 0; nt < 16; nt++) {
                int off = (ncol0 + nt*8 + g4)*144 + koff;
                uint32_t bh2[2];
                bh2[0] = *(const uint32_t*)(sFh + off);
                bh2[1] = *(const uint32_t*)(sFh + off + 16);
                mma16816(sacc[nt], ah, bh2);
            }
        }
    }

    float sum0 = 0.f, sq0 = 0.f, sum1 = 0.f, sq1 = 0.f;
#pragma unroll
    for (int nt = 0; nt < 16; nt++) {
        int col = ncol0 + nt*8 + t4*2;
        float2 q0 = *(const float2*)(qin + (size_t)gr0*FF + col);
        float2 q1 = *(const float2*)(qin + (size_t)gr1*FF + col);
        sacc[nt][0] += q0.x; sacc[nt][1] += q0.y;
        sacc[nt][2] += q1.x; sacc[nt][3] += q1.y;
        sum0 += sacc[nt][0] + sacc[nt][1];
        sq0  += sacc[nt][0]*sacc[nt][0] + sacc[nt][1]*sacc[nt][1];
        sum1 += sacc[nt][2] + sacc[nt][3];
        sq1  += sacc[nt][2]*sacc[nt][2] + sacc[nt][3]*sacc[nt][3];
    }
    sum0 += __shfl_xor_sync(0xffffffffu, sum0, 1);
    sum0 += __shfl_xor_sync(0xffffffffu, sum0, 2);
    sq0  += __shfl_xor_sync(0xffffffffu, sq0, 1);
    sq0  += __shfl_xor_sync(0xffffffffu, sq0, 2);
    sum1 += __shfl_xor_sync(0xffffffffu, sum1, 1);
    sum1 += __shfl_xor_sync(0xffffffffu, sum1, 2);
    sq1  += __shfl_xor_sync(0xffffffffu, sq1, 1);
    sq1  += __shfl_xor_sync(0xffffffffu, sq1, 2);

    __syncthreads();
    if (t4 == 0) {
        red_s[r0][half] = sum0;     red_q[r0][half] = sq0;
        red_s[r0 + 8][half] = sum1; red_q[r0 + 8][half] = sq1;
    }
    __syncthreads();

    float s0 = red_s[r0][0] + red_s[r0][1];
    float qq0 = red_q[r0][0] + red_q[r0][1];
    float s1 = red_s[r0 + 8][0] + red_s[r0 + 8][1];
    float qq1 = red_q[r0 + 8][0] + red_q[r0 + 8][1];

    float mu0 = s0 * (1.f/256.f);
    float mu1 = s1 * (1.f/256.f);
    float rstd0 = rsqrtf(qq0 * (1.f/256.f) - mu0*mu0 + 1e-6f);
    float rstd1 = rsqrtf(qq1 * (1.f/256.f) - mu1*mu1 + 1e-6f);

#pragma unroll
    for (int nt = 0; nt < 16; nt++) {
        int col = ncol0 + nt*8 + t4*2;
        float2 g = *(const float2*)(lng + col);
        float2 bt = *(const float2*)(lnb + col);
        float2 o0, o1;
        o0.x = (sacc[nt][0] - mu0)*rstd0*g.x + bt.x;
        o0.y = (sacc[nt][1] - mu0)*rstd0*g.y + bt.y;
        o1.x = (sacc[nt][2] - mu1)*rstd1*g.x + bt.x;
        o1.y = (sacc[nt][3] - mu1)*rstd1*g.y + bt.y;
        *(float2*)(out + (size_t)gr0*FF + col) = o0;
        *(float2*)(out + (size_t)gr1*FF + col) = o1;
    }
}

// ---------------------------------------------------------------------------
extern "C" void kernel_launch(void* const* d_in, const int* in_sizes, int n_in,
                              void* d_out, int out_size)
{
    const float* q    = (const float*)d_in[0];
    const float* v    = (const float*)d_in[2];   // d_in[1] (k) unused by model
    const float* w_qs = (const float*)d_in[3];
    const float* w_vs = (const float*)d_in[4];
    const float* w1   = (const float*)d_in[5];
    const float* b1   = (const float*)d_in[6];
    const float* w2   = (const float*)d_in[7];
    const float* b2   = (const float*)d_in[8];
    const float* fcw  = (const float*)d_in[9];
    const float* lng  = (const float*)d_in[10];
    const float* lnb  = (const float*)d_in[11];
    float* out = (float*)d_out;

    cudaFuncSetAttribute(k_proj_mma,  cudaFuncAttributeMaxDynamicSharedMemorySize, PJ_SMEM);
    cudaFuncSetAttribute(k_final_mma, cudaFuncAttributeMaxDynamicSharedMemorySize, FN_SMEM);

    k_prep_all <<<912, 256>>>(w2, w_qs, w_vs, fcw, w1);
    k_proj_mma <<<dim3(500, 2),    256, PJ_SMEM>>>(q, v, b1);
    k_attn_mma <<<dim3(4, HH, BB), 256>>>(b2);
    k_final_mma<<<500,             256, FN_SMEM>>>(q, lng, lnb, out);
}

// round 15
// speedup vs baseline: 1.0465x; 1.0465x over previous
#include <cuda_runtime.h>
#include <cuda_bf16.h>
#include <cstdint>

// MultiHeadDenseSynthesizer: B=64, L=500, F=256, H=4, dk=64
// Round 14: revert k_proj to round-12 (per-head, M=128) after round-13
// regression; k_attn pipelines 128 j-cols/stage (4 stages, half the barriers).

#define BB  64
#define LL  500
#define FF  256
#define HH  4
#define DKK 64
#define BLL (BB*LL)
#define BH  (BB*HH)
#define LPAD 512

// ---------------- device scratch (zero-initialized at load) ----------------
__device__ __nv_bfloat16 g_ctxb[BLL*FF];   // attn out, bf16, [b*L+l][f]
__device__ uint4 g_wt_h4[BH*LL*DKK/8];     // W  [bh][l][d] bf16
__device__ uint4 g_vT_h4[BH*DKK*LPAD/8];   // Vt [bh][d][j] bf16
__device__ uint4 g_w2T_h4[LPAD*DKK/8];     // w2T [j][d] bf16
__device__ uint4 g_wqsT4h[FF*FF/8];        // [n][k] bf16
__device__ uint4 g_wvsT4h[FF*FF/8];
__device__ uint4 g_fcwT4h[FF*FF/8];
__device__ uint4 g_w1T4h[DKK*DKK/8];

__device__ __forceinline__ uint32_t pack_hi2(float x, float y) {
    __nv_bfloat162 t = __float22bfloat162_rn(make_float2(x, y));
    return *(uint32_t*)&t;
}
__device__ __forceinline__ void mma16816(float c[4], const uint32_t a[4], const uint32_t b[2]) {
    asm volatile(
        "mma.sync.aligned.m16n8k16.row.col.f32.bf16.bf16.f32 "
        "{%0,%1,%2,%3}, {%4,%5,%6,%7}, {%8,%9}, {%0,%1,%2,%3};"
        : "+f"(c[0]), "+f"(c[1]), "+f"(c[2]), "+f"(c[3])
        : "r"(a[0]), "r"(a[1]), "r"(a[2]), "r"(a[3]), "r"(b[0]), "r"(b[1]));
}
__device__ __forceinline__ void cpa16(uint32_t s, const void* g) {
    asm volatile("cp.async.cg.shared.global [%0], [%1], 16;" :: "r"(s), "l"(g));
}
#define CPA_COMMIT() asm volatile("cp.async.commit_group;" ::: "memory")
#define CPA_WAIT0()  asm volatile("cp.async.wait_group 0;"  ::: "memory")

// ---------------------------------------------------------------------------
// k_prep_all: all weight transposes -> bf16.
// ---------------------------------------------------------------------------
__global__ void k_prep_all(const float* __restrict__ w2, const float* __restrict__ wqs,
                           const float* __restrict__ wvs, const float* __restrict__ fcw,
                           const float* __restrict__ w1)
{
    int bx = blockIdx.x, tid = threadIdx.x;
    float v; __nv_bfloat16* dh; int idx;
    if (bx < 128) {
        idx = bx*256 + tid;                       // j*64 + d
        int j = idx >> 6, d = idx & 63;
        v = (j < LL) ? w2[d*LL + j] : 0.f;
        dh = (__nv_bfloat16*)g_w2T_h4;
    } else if (bx < 384) {
        idx = (bx - 128)*256 + tid;               // n*256 + k
        int n = idx >> 8, k = idx & 255;
        v = wqs[k*FF + n];
        dh = (__nv_bfloat16*)g_wqsT4h;
    } else if (bx < 640) {
        idx = (bx - 384)*256 + tid;
        int n = idx >> 8, k = idx & 255;
        v = wvs[k*FF + n];
        dh = (__nv_bfloat16*)g_wvsT4h;
    } else if (bx < 896) {
        idx = (bx - 640)*256 + tid;
        int n = idx >> 8, k = idx & 255;
        v = fcw[k*FF + n];
        dh = (__nv_bfloat16*)g_fcwT4h;
    } else {
        idx = (bx - 896)*256 + tid;               // n*64 + k
        int n = idx >> 6, k = idx & 63;
        v = w1[k*DKK + n];
        dh = (__nv_bfloat16*)g_w1T4h;
    }
    dh[idx] = __float2bfloat16(v);
}

// ---------------------------------------------------------------------------
// Kernel 1: projections (round-12 version). grid (250, 4, 2), 256 thr, M=128.
// ---------------------------------------------------------------------------
#define PJ_WPITCH 528
#define PJ_W1OFF  (64*PJ_WPITCH)            // 33792
#define PJ_B1OFF  (PJ_W1OFF + 64*144)       // 43008
#define PJ_SMEM   (PJ_B1OFF + 256)          // 43264

__global__ void __launch_bounds__(256)
k_proj_mma(const float* __restrict__ qin, const float* __restrict__ vin,
           const float* __restrict__ b1)
{
    extern __shared__ char smem[];
    char* sWh  = smem;
    char* sW1h = smem + PJ_W1OFF;
    float* b1s = (float*)(smem + PJ_B1OFF);
    float* vtr = (float*)smem;          // mode1 alias: [64][132] fp32

    const int tid  = threadIdx.x;
    const int lane = tid & 31, wid = tid >> 5;
    const int g4 = lane >> 2, t4 = lane & 3;
    const int m0 = blockIdx.x * 128;
    const int h  = blockIdx.y;
    const int mode = blockIdx.z;
    const float* A = mode ? vin : qin;
    const uint4* WTh = mode ? g_wvsT4h : g_wqsT4h;

    for (int idx = tid; idx < 2048; idx += 256) {
        int row = idx >> 5, c16 = idx & 31;
        *(uint4*)(sWh + row*PJ_WPITCH + c16*16) = WTh[(h*64 + row)*32 + c16];
    }
    if (!mode) {
        for (int idx = tid; idx < 512; idx += 256) {
            int row = idx >> 3, gq = idx & 7;
            *(uint4*)(sW1h + row*144 + gq*16) = g_w1T4h[row*8 + gq];
        }
        if (tid < 64) b1s[tid] = b1[tid];
    }
    __syncthreads();

    const int r0 = wid*16 + g4;
    const int gr0 = m0 + r0, gr1 = gr0 + 8;

    float sacc[8][4];
#pragma unroll
    for (int nt = 0; nt < 8; nt++)
#pragma unroll
        for (int e = 0; e < 4; e++) sacc[nt][e] = 0.f;

#pragma unroll 4
    for (int kt = 0; kt < 16; kt++) {
        int c0 = kt*16 + t4*2;
        uint32_t ah[4];
        float2 f;
        f = *(const float2*)(A + (size_t)gr0*FF + c0);     ah[0] = pack_hi2(f.x, f.y);
        f = *(const float2*)(A + (size_t)gr1*FF + c0);     ah[1] = pack_hi2(f.x, f.y);
        f = *(const float2*)(A + (size_t)gr0*FF + c0 + 8); ah[2] = pack_hi2(f.x, f.y);
        f = *(const float2*)(A + (size_t)gr1*FF + c0 + 8); ah[3] = pack_hi2(f.x, f.y);
#pragma unroll
        for (int nt = 0; nt < 8; nt++) {
            int off = (nt*8 + g4)*PJ_WPITCH + c0*2;
            uint32_t bh2[2];
            bh2[0] = *(const uint32_t*)(sWh + off);
            bh2[1] = *(const uint32_t*)(sWh + off + 16);
            mma16816(sacc[nt], ah, bh2);
        }
    }

    if (mode) {
        // ---- transpose vh via smem -> g_vT [bh][d][j] bf16
        __syncthreads();
#pragma unroll
        for (int nt = 0; nt < 8; nt++) {
            int d0 = nt*8 + t4*2;
            vtr[d0*132 + r0]         = sacc[nt][0];
            vtr[(d0+1)*132 + r0]     = sacc[nt][1];
            vtr[d0*132 + r0 + 8]     = sacc[nt][2];
            vtr[(d0+1)*132 + r0 + 8] = sacc[nt][3];
        }
        __syncthreads();
        __nv_bfloat16* vTh = (__nv_bfloat16*)g_vT_h4;
        for (int idx = tid; idx < 4096; idx += 256) {
            int d = idx >> 6, jp = idx & 63;
            int gj = m0 + 2*jp;
            int b = gj / LL, p = gj - b*LL;   // pairs never cross batch (500 even)
            size_t a = ((size_t)((b*HH + h)*DKK + d))*LPAD + p;
            *(uint32_t*)(vTh + a) = pack_hi2(vtr[d*132 + 2*jp], vtr[d*132 + 2*jp + 1]);
        }
        return;
    }

    // ---- hand-off: qh C-frags -> A-frags
    uint32_t ph[4][4];
#pragma unroll
    for (int nt = 0; nt < 8; nt++) {
        int kt = nt >> 1, i0 = (nt & 1) * 2;
        ph[kt][i0]     = pack_hi2(sacc[nt][0], sacc[nt][1]);
        ph[kt][i0 + 1] = pack_hi2(sacc[nt][2], sacc[nt][3]);
    }

    float s2[8][4];
#pragma unroll
    for (int nt = 0; nt < 8; nt++) {
        int col = nt*8 + t4*2;
        s2[nt][0] = s2[nt][2] = b1s[col];
        s2[nt][1] = s2[nt][3] = b1s[col + 1];
    }
#pragma unroll
    for (int kt = 0; kt < 4; kt++) {
#pragma unroll
        for (int nt = 0; nt < 8; nt++) {
            int off = (nt*8 + g4)*144 + (kt*16 + t4*2)*2;
            uint32_t bh2[2];
            bh2[0] = *(const uint32_t*)(sW1h + off);
            bh2[1] = *(const uint32_t*)(sW1h + off + 16);
            mma16816(s2[nt], ph[kt], bh2);
        }
    }

    // relu + store g_wt (bf16)
    __nv_bfloat16* wth = (__nv_bfloat16*)g_wt_h4;
    int b0_ = gr0 / LL, l0_ = gr0 - b0_*LL;
    int b1_ = gr1 / LL, l1_ = gr1 - b1_*LL;
    size_t base0 = ((size_t)((b0_*HH + h)*LL + l0_))*DKK;
    size_t base1 = ((size_t)((b1_*HH + h)*LL + l1_))*DKK;
#pragma unroll
    for (int nt = 0; nt < 8; nt++) {
        int d = nt*8 + t4*2;
        *(uint32_t*)(wth + base0 + d) =
            pack_hi2(fmaxf(s2[nt][0], 0.f), fmaxf(s2[nt][1], 0.f));
        *(uint32_t*)(wth + base1 + d) =
            pack_hi2(fmaxf(s2[nt][2], 0.f), fmaxf(s2[nt][3], 0.f));
    }
}

// ---------------------------------------------------------------------------
// Kernel 2: attention, 128 j-cols per pipeline stage (4 stages), double-
// buffered cp.async. grid (4, H, B), 256 thr. Dynamic smem (75.8 KB).
// smem: [0, 2*ASTAGE) W2 buffers; [2*ASTAGE, 4*ASTAGE) V buffers; then b2.
// Each 18432-byte stage tile = two 64-col sub-tiles of 9216 bytes.
// ---------------------------------------------------------------------------
#define SPITCH 144
#define ASUB   (64*SPITCH)       // 9216
#define ASTAGE (2*ASUB)          // 18432
#define ATT_B2OFF (4*ASTAGE)     // 73728
#define ATT_SMEM  (ATT_B2OFF + 2048)   // 75776

__global__ void __launch_bounds__(256)
k_attn_mma(const float* __restrict__ b2)
{
    extern __shared__ char smem[];
    float* b2all = (float*)(smem + ATT_B2OFF);
    const uint32_t sW2a = (uint32_t)__cvta_generic_to_shared(smem);
    const uint32_t sVa  = sW2a + 2*ASTAGE;

    const int tid  = threadIdx.x;
    const int lane = tid & 31, wid = tid >> 5;
    const int g4 = lane >> 2, t4 = lane & 3;
    const int l0 = blockIdx.x * 128;
    const int h  = blockIdx.y, b = blockIdx.z;
    const int bh = b*HH + h;
    const int r0 = l0 + wid*16 + g4;

#pragma unroll
    for (int it = 0; it < 2; it++) {
        int i = tid + it*256;
        b2all[i] = (i < LL) ? b2[i] : 0.f;
    }

    const __nv_bfloat16* wth = (const __nv_bfloat16*)g_wt_h4;
    uint32_t aWh[4][4];
    {
        const bool v0 = (r0 < LL), v1 = (r0 + 8 < LL);
        size_t base0 = (size_t)(bh*LL + r0)*DKK;
        size_t base1 = (size_t)(bh*LL + r0 + 8)*DKK;
#pragma unroll
        for (int kt = 0; kt < 4; kt++) {
            int c0 = kt*16 + t4*2, c8 = c0 + 8;
            aWh[kt][0] = v0 ? *(const uint32_t*)(wth + base0 + c0) : 0u;
            aWh[kt][1] = v1 ? *(const uint32_t*)(wth + base1 + c0) : 0u;
            aWh[kt][2] = v0 ? *(const uint32_t*)(wth + base0 + c8) : 0u;
            aWh[kt][3] = v1 ? *(const uint32_t*)(wth + base1 + c8) : 0u;
        }
    }

    float oacc[8][4];
#pragma unroll
    for (int nt = 0; nt < 8; nt++)
#pragma unroll
        for (int e = 0; e < 4; e++) oacc[nt][e] = 0.f;
    float dp0 = 0.f, dp1 = 0.f;

    // stage 0 prefetch: W2 rows 0..127, V sub-tiles 0..1 (j 0..127)
#pragma unroll
    for (int it = 0; it < 4; it++) {
        int idx = tid + it*256;                    // 0..1023
        {   // W2: row rr (j), granule gg (d)
            int rr = idx >> 3, gg = idx & 7;
            cpa16(sW2a + rr*SPITCH + gg*16, &g_w2T_h4[(size_t)rr*8 + gg]);
        }
        {   // V: sub s, row d, granule gg (j)
            int s = idx >> 9, rem = idx & 511;
            int d = rem >> 3, gg = rem & 7;
            cpa16(sVa + s*ASUB + d*SPITCH + gg*16,
                  &g_vT_h4[(size_t)(bh*DKK + d)*(LPAD/8) + s*8 + gg]);
        }
    }
    CPA_COMMIT();

    for (int st = 0; st < 4; st++) {
        const int buf = st & 1;
        CPA_WAIT0();
        __syncthreads();
        if (st < 3) {
            const int jn = (st + 1) * 128;
            const uint32_t dW2 = sW2a + (buf ^ 1)*ASTAGE;
            const uint32_t dV  = sVa  + (buf ^ 1)*ASTAGE;
#pragma unroll
            for (int it = 0; it < 4; it++) {
                int idx = tid + it*256;
                {
                    int rr = idx >> 3, gg = idx & 7;
                    cpa16(dW2 + rr*SPITCH + gg*16,
                          &g_w2T_h4[(size_t)(jn + rr)*8 + gg]);
                }
                {
                    int s = idx >> 9, rem = idx & 511;
                    int d = rem >> 3, gg = rem & 7;
                    cpa16(dV + s*ASUB + d*SPITCH + gg*16,
                          &g_vT_h4[(size_t)(bh*DKK + d)*(LPAD/8) + (jn >> 3) + s*8 + gg]);
                }
            }
            CPA_COMMIT();
        }

#pragma unroll
        for (int sub = 0; sub < 2; sub++) {
            const int j0 = st*128 + sub*64;
            const char* w2b = smem + buf*ASTAGE + sub*ASUB;
            const char* vb  = smem + 2*ASTAGE + buf*ASTAGE + sub*ASUB;

            float sacc[8][4];
#pragma unroll
            for (int nt = 0; nt < 8; nt++)
#pragma unroll
                for (int e = 0; e < 4; e++) sacc[nt][e] = 0.f;

#pragma unroll
            for (int kt = 0; kt < 4; kt++) {
#pragma unroll
                for (int nt = 0; nt < 8; nt++) {
                    int off = (nt*8 + g4)*SPITCH + (kt*16 + t4*2)*2;
                    uint32_t bh2[2];
                    bh2[0] = *(const uint32_t*)(w2b + off);
                    bh2[1] = *(const uint32_t*)(w2b + off + 16);
                    mma16816(sacc[nt], aWh[kt], bh2);
                }
            }

            uint32_t phA[4][4];
#pragma unroll
            for (int nt = 0; nt < 8; nt++) {
                int jl = nt*8 + t4*2;
                int jg = j0 + jl;
                float bb0 = b2all[jg], bb1 = b2all[jg + 1];
                float p0 = (jg     < LL) ? __expf(sacc[nt][0] + bb0) : 0.f;
                float p1 = (jg + 1 < LL) ? __expf(sacc[nt][1] + bb1) : 0.f;
                float p2 = (jg     < LL) ? __expf(sacc[nt][2] + bb0) : 0.f;
                float p3 = (jg + 1 < LL) ? __expf(sacc[nt][3] + bb1) : 0.f;
                dp0 += p0 + p1;
                dp1 += p2 + p3;
                int kt = nt >> 1, i0 = (nt & 1) * 2;
                phA[kt][i0]     = pack_hi2(p0, p1);
                phA[kt][i0 + 1] = pack_hi2(p2, p3);
            }

#pragma unroll
            for (int kt = 0; kt < 4; kt++) {
#pragma unroll
                for (int nt = 0; nt < 8; nt++) {
                    int off = (nt*8 + g4)*SPITCH + (kt*16 + t4*2)*2;
                    uint32_t bvh[2];
                    bvh[0] = *(const uint32_t*)(vb + off);
                    bvh[1] = *(const uint32_t*)(vb + off + 16);
                    mma16816(oacc[nt], phA[kt], bvh);
                }
            }
        }
    }

    dp0 += __shfl_xor_sync(0xffffffffu, dp0, 1);
    dp0 += __shfl_xor_sync(0xffffffffu, dp0, 2);
    dp1 += __shfl_xor_sync(0xffffffffu, dp1, 1);
    dp1 += __shfl_xor_sync(0xffffffffu, dp1, 2);
    float inv0 = 1.f / dp0, inv1 = 1.f / dp1;

    if (r0 < LL) {
        __nv_bfloat16* dst = g_ctxb + ((size_t)(b*LL + r0))*FF + h*DKK + t4*2;
#pragma unroll
        for (int nt = 0; nt < 8; nt++)
            *(uint32_t*)(dst + nt*8) = pack_hi2(oacc[nt][0]*inv0, oacc[nt][1]*inv0);
    }
    if (r0 + 8 < LL) {
        __nv_bfloat16* dst = g_ctxb + ((size_t)(b*LL + r0 + 8))*FF + h*DKK + t4*2;
#pragma unroll
        for (int nt = 0; nt < 8; nt++)
            *(uint32_t*)(dst + nt*8) = pack_hi2(oacc[nt][2]*inv1, oacc[nt][3]*inv1);
    }
}

// ---------------------------------------------------------------------------
// Kernel 3: out = LN(ctx @ fcwT^T + q). grid 500 (M=64/CTA), 256 thr.
// (round-12 version, unchanged)
// ---------------------------------------------------------------------------
#define FTILE (256*144)          // 36864
#define FN_SMEM (2*FTILE)        // 73728

__global__ void __launch_bounds__(256)
k_final_mma(const float* __restrict__ qin, const float* __restrict__ lng,
            const float* __restrict__ lnb, float* __restrict__ out)
{
    extern __shared__ char smem[];
    __shared__ float red_s[64][2], red_q[64][2];
    const uint32_t sFa = (uint32_t)__cvta_generic_to_shared(smem);

    const int tid  = threadIdx.x;
    const int lane = tid & 31, wid = tid >> 5;
    const int g4 = lane >> 2, t4 = lane & 3;
    const int half = wid >> 2, wrow = wid & 3;
    const int ncol0 = half * 128;
    const int m0 = blockIdx.x * 64;
    const int r0 = wrow*16 + g4;
    const int gr0 = m0 + r0, gr1 = gr0 + 8;
    const __nv_bfloat16* ctxb = g_ctxb;

    float sacc[16][4];
#pragma unroll
    for (int nt = 0; nt < 16; nt++)
#pragma unroll
        for (int e = 0; e < 4; e++) sacc[nt][e] = 0.f;

#pragma unroll
    for (int it = 0; it < 8; it++) {
        int idx = tid + it*256;
        int row = idx >> 3, gq = idx & 7;
        cpa16(sFa + row*144 + gq*16, &g_fcwT4h[row*32 + gq]);
    }
    CPA_COMMIT();

    for (int kc = 0; kc < 4; kc++) {
        const int buf = kc & 1;
        CPA_WAIT0();
        __syncthreads();
        if (kc < 3) {
            const uint32_t dF = sFa + (buf ^ 1)*FTILE;
#pragma unroll
            for (int it = 0; it < 8; it++) {
                int idx = tid + it*256;
                int row = idx >> 3, gq = idx & 7;
                cpa16(dF + row*144 + gq*16, &g_fcwT4h[row*32 + (kc+1)*8 + gq]);
            }
            CPA_COMMIT();
        }
        const char* sFh = smem + buf*FTILE;

#pragma unroll
        for (int kt = 0; kt < 4; kt++) {
            int cg = kc*64 + kt*16 + t4*2;
            uint32_t ah[4];
            ah[0] = *(const uint32_t*)(ctxb + (size_t)gr0*FF + cg);
            ah[1] = *(const uint32_t*)(ctxb + (size_t)gr1*FF + cg);
            ah[2] = *(const uint32_t*)(ctxb + (size_t)gr0*FF + cg + 8);
            ah[3] = *(const uint32_t*)(ctxb + (size_t)gr1*FF + cg + 8);
            int koff = (kt*16 + t4*2)*2;
#pragma unroll
            for (int nt = 0; nt < 16; nt++) {
                int off = (ncol0 + nt*8 + g4)*144 + koff;
                uint32_t bh2[2];
                bh2[0] = *(const uint32_t*)(sFh + off);
                bh2[1] = *(const uint32_t*)(sFh + off + 16);
                mma16816(sacc[nt], ah, bh2);
            }
        }
    }

    float sum0 = 0.f, sq0 = 0.f, sum1 = 0.f, sq1 = 0.f;
#pragma unroll
    for (int nt = 0; nt < 16; nt++) {
        int col = ncol0 + nt*8 + t4*2;
        float2 q0 = *(const float2*)(qin + (size_t)gr0*FF + col);
        float2 q1 = *(const float2*)(qin + (size_t)gr1*FF + col);
        sacc[nt][0] += q0.x; sacc[nt][1] += q0.y;
        sacc[nt][2] += q1.x; sacc[nt][3] += q1.y;
        sum0 += sacc[nt][0] + sacc[nt][1];
        sq0  += sacc[nt][0]*sacc[nt][0] + sacc[nt][1]*sacc[nt][1];
        sum1 += sacc[nt][2] + sacc[nt][3];
        sq1  += sacc[nt][2]*sacc[nt][2] + sacc[nt][3]*sacc[nt][3];
    }
    sum0 += __shfl_xor_sync(0xffffffffu, sum0, 1);
    sum0 += __shfl_xor_sync(0xffffffffu, sum0, 2);
    sq0  += __shfl_xor_sync(0xffffffffu, sq0, 1);
    sq0  += __shfl_xor_sync(0xffffffffu, sq0, 2);
    sum1 += __shfl_xor_sync(0xffffffffu, sum1, 1);
    sum1 += __shfl_xor_sync(0xffffffffu, sum1, 2);
    sq1  += __shfl_xor_sync(0xffffffffu, sq1, 1);
    sq1  += __shfl_xor_sync(0xffffffffu, sq1, 2);

    __syncthreads();
    if (t4 == 0) {
        red_s[r0][half] = sum0;     red_q[r0][half] = sq0;
        red_s[r0 + 8][half] = sum1; red_q[r0 + 8][half] = sq1;
    }
    __syncthreads();

    float s0 = red_s[r0][0] + red_s[r0][1];
    float qq0 = red_q[r0][0] + red_q[r0][1];
    float s1 = red_s[r0 + 8][0] + red_s[r0 + 8][1];
    float qq1 = red_q[r0 + 8][0] + red_q[r0 + 8][1];

    float mu0 = s0 * (1.f/256.f);
    float mu1 = s1 * (1.f/256.f);
    float rstd0 = rsqrtf(qq0 * (1.f/256.f) - mu0*mu0 + 1e-6f);
    float rstd1 = rsqrtf(qq1 * (1.f/256.f) - mu1*mu1 + 1e-6f);

#pragma unroll
    for (int nt = 0; nt < 16; nt++) {
        int col = ncol0 + nt*8 + t4*2;
        float2 g = *(const float2*)(lng + col);
        float2 bt = *(const float2*)(lnb + col);
        float2 o0, o1;
        o0.x = (sacc[nt][0] - mu0)*rstd0*g.x + bt.x;
        o0.y = (sacc[nt][1] - mu0)*rstd0*g.y + bt.y;
        o1.x = (sacc[nt][2] - mu1)*rstd1*g.x + bt.x;
        o1.y = (sacc[nt][3] - mu1)*rstd1*g.y + bt.y;
        *(float2*)(out + (size_t)gr0*FF + col) = o0;
        *(float2*)(out + (size_t)gr1*FF + col) = o1;
    }
}

// ---------------------------------------------------------------------------
extern "C" void kernel_launch(void* const* d_in, const int* in_sizes, int n_in,
                              void* d_out, int out_size)
{
    const float* q    = (const float*)d_in[0];
    const float* v    = (const float*)d_in[2];   // d_in[1] (k) unused by model
    const float* w_qs = (const float*)d_in[3];
    const float* w_vs = (const float*)d_in[4];
    const float* w1   = (const float*)d_in[5];
    const float* b1   = (const float*)d_in[6];
    const float* w2   = (const float*)d_in[7];
    const float* b2   = (const float*)d_in[8];
    const float* fcw  = (const float*)d_in[9];
    const float* lng  = (const float*)d_in[10];
    const float* lnb  = (const float*)d_in[11];
    float* out = (float*)d_out;

    cudaFuncSetAttribute(k_proj_mma,  cudaFuncAttributeMaxDynamicSharedMemorySize, PJ_SMEM);
    cudaFuncSetAttribute(k_attn_mma,  cudaFuncAttributeMaxDynamicSharedMemorySize, ATT_SMEM);
    cudaFuncSetAttribute(k_final_mma, cudaFuncAttributeMaxDynamicSharedMemorySize, FN_SMEM);

    k_prep_all <<<912, 256>>>(w2, w_qs, w_vs, fcw, w1);
    k_proj_mma <<<dim3(250, HH, 2), 256, PJ_SMEM>>>(q, v, b1);
    k_attn_mma <<<dim3(4, HH, BB),  256, ATT_SMEM>>>(b2);
    k_final_mma<<<500,              256, FN_SMEM>>>(q, lng, lnb, out);
}

// round 17
// speedup vs baseline: 1.0469x; 1.0003x over previous
#include <cuda_runtime.h>
#include <cuda_bf16.h>
#include <cstdint>

// MultiHeadDenseSynthesizer: B=64, L=500, F=256, H=4, dk=64
// Round 16: attack exposed A-operand LDG latency.
//  - prep converts q/v to bf16 (g_qb/g_vb), bit-identical rounding
//  - k_proj: depth-2 A-frag prefetch pipeline (bf16 A loads)
//  - k_final: ctx tile staged via cp.async alongside fcw
//  - k_attn: round-12 version (best-known)

#define BB  64
#define LL  500
#define FF  256
#define HH  4
#define DKK 64
#define BLL (BB*LL)
#define BH  (BB*HH)
#define LPAD 512

// ---------------- device scratch (zero-initialized at load) ----------------
__device__ __nv_bfloat16 g_ctxb[BLL*FF];   // attn out, bf16, [b*L+l][f]
__device__ uint4 g_qb4[BLL*FF/8];          // q bf16
__device__ uint4 g_vb4[BLL*FF/8];          // v bf16
__device__ uint4 g_wt_h4[BH*LL*DKK/8];     // W  [bh][l][d] bf16
__device__ uint4 g_vT_h4[BH*DKK*LPAD/8];   // Vt [bh][d][j] bf16
__device__ uint4 g_w2T_h4[LPAD*DKK/8];     // w2T [j][d] bf16
__device__ uint4 g_wqsT4h[FF*FF/8];        // [n][k] bf16
__device__ uint4 g_wvsT4h[FF*FF/8];
__device__ uint4 g_fcwT4h[FF*FF/8];
__device__ uint4 g_w1T4h[DKK*DKK/8];

__device__ __forceinline__ uint32_t pack_hi2(float x, float y) {
    __nv_bfloat162 t = __float22bfloat162_rn(make_float2(x, y));
    return *(uint32_t*)&t;
}
__device__ __forceinline__ void mma16816(float c[4], const uint32_t a[4], const uint32_t b[2]) {
    asm volatile(
        "mma.sync.aligned.m16n8k16.row.col.f32.bf16.bf16.f32 "
        "{%0,%1,%2,%3}, {%4,%5,%6,%7}, {%8,%9}, {%0,%1,%2,%3};"
        : "+f"(c[0]), "+f"(c[1]), "+f"(c[2]), "+f"(c[3])
        : "r"(a[0]), "r"(a[1]), "r"(a[2]), "r"(a[3]), "r"(b[0]), "r"(b[1]));
}
__device__ __forceinline__ void cpa16(uint32_t s, const void* g) {
    asm volatile("cp.async.cg.shared.global [%0], [%1], 16;" :: "r"(s), "l"(g));
}
#define CPA_COMMIT() asm volatile("cp.async.commit_group;" ::: "memory")
#define CPA_WAIT0()  asm volatile("cp.async.wait_group 0;"  ::: "memory")

// ---------------------------------------------------------------------------
// k_prep_all: weight transposes -> bf16; q/v -> bf16.
// blocks [0,128): w2T, [128,384): wqsT, [384,640): wvsT, [640,896): fcwT,
// [896,912): w1T, [912,2912): q->bf16, [2912,4912): v->bf16.
// ---------------------------------------------------------------------------
__global__ void k_prep_all(const float* __restrict__ w2, const float* __restrict__ wqs,
                           const float* __restrict__ wvs, const float* __restrict__ fcw,
                           const float* __restrict__ w1, const float* __restrict__ qin,
                           const float* __restrict__ vin)
{
    int bx = blockIdx.x, tid = threadIdx.x;
    if (bx >= 912) {
        const float* src = (bx < 2912) ? qin : vin;
        uint4* dstA = (bx < 2912) ? g_qb4 : g_vb4;
        int seg = (bx < 2912) ? (bx - 912) : (bx - 2912);
        int base = seg*4096 + tid*16;
        const float4* s4 = (const float4*)(src + base);
        float4 f0 = s4[0], f1 = s4[1], f2 = s4[2], f3 = s4[3];
        uint4 o0, o1;
        o0.x = pack_hi2(f0.x, f0.y); o0.y = pack_hi2(f0.z, f0.w);
        o0.z = pack_hi2(f1.x, f1.y); o0.w = pack_hi2(f1.z, f1.w);
        o1.x = pack_hi2(f2.x, f2.y); o1.y = pack_hi2(f2.z, f2.w);
        o1.z = pack_hi2(f3.x, f3.y); o1.w = pack_hi2(f3.z, f3.w);
        uint4* d = dstA + (base >> 3);
        d[0] = o0; d[1] = o1;
        return;
    }
    float v; __nv_bfloat16* dh; int idx;
    if (bx < 128) {
        idx = bx*256 + tid;                       // j*64 + d
        int j = idx >> 6, d = idx & 63;
        v = (j < LL) ? w2[d*LL + j] : 0.f;
        dh = (__nv_bfloat16*)g_w2T_h4;
    } else if (bx < 384) {
        idx = (bx - 128)*256 + tid;               // n*256 + k
        int n = idx >> 8, k = idx & 255;
        v = wqs[k*FF + n];
        dh = (__nv_bfloat16*)g_wqsT4h;
    } else if (bx < 640) {
        idx = (bx - 384)*256 + tid;
        int n = idx >> 8, k = idx & 255;
        v = wvs[k*FF + n];
        dh = (__nv_bfloat16*)g_wvsT4h;
    } else if (bx < 896) {
        idx = (bx - 640)*256 + tid;
        int n = idx >> 8, k = idx & 255;
        v = fcw[k*FF + n];
        dh = (__nv_bfloat16*)g_fcwT4h;
    } else {
        idx = (bx - 896)*256 + tid;               // n*64 + k
        int n = idx >> 6, k = idx & 63;
        v = w1[k*DKK + n];
        dh = (__nv_bfloat16*)g_w1T4h;
    }
    dh[idx] = __float2bfloat16(v);
}

// ---------------------------------------------------------------------------
// Kernel 1: projections. grid (250, 4, 2), 256 thr, M=128, bf16 A with
// depth-2 frag prefetch.
// ---------------------------------------------------------------------------
#define PJ_WPITCH 528
#define PJ_W1OFF  (64*PJ_WPITCH)            // 33792
#define PJ_B1OFF  (PJ_W1OFF + 64*144)       // 43008
#define PJ_SMEM   (PJ_B1OFF + 256)          // 43264

__global__ void __launch_bounds__(256)
k_proj_mma(const float* __restrict__ b1)
{
    extern __shared__ char smem[];
    char* sWh  = smem;
    char* sW1h = smem + PJ_W1OFF;
    float* b1s = (float*)(smem + PJ_B1OFF);
    float* vtr = (float*)smem;          // mode1 alias: [64][132] fp32

    const int tid  = threadIdx.x;
    const int lane = tid & 31, wid = tid >> 5;
    const int g4 = lane >> 2, t4 = lane & 3;
    const int m0 = blockIdx.x * 128;
    const int h  = blockIdx.y;
    const int mode = blockIdx.z;
    const __nv_bfloat16* Ab = (const __nv_bfloat16*)(mode ? g_vb4 : g_qb4);
    const uint4* WTh = mode ? g_wvsT4h : g_wqsT4h;

    for (int idx = tid; idx < 2048; idx += 256) {
        int row = idx >> 5, c16 = idx & 31;
        *(uint4*)(sWh + row*PJ_WPITCH + c16*16) = WTh[(h*64 + row)*32 + c16];
    }
    if (!mode) {
        for (int idx = tid; idx < 512; idx += 256) {
            int row = idx >> 3, gq = idx & 7;
            *(uint4*)(sW1h + row*144 + gq*16) = g_w1T4h[row*8 + gq];
        }
        if (tid < 64) b1s[tid] = b1[tid];
    }
    __syncthreads();

    const int r0 = wid*16 + g4;
    const int gr0 = m0 + r0, gr1 = gr0 + 8;
    const size_t rowA0 = (size_t)gr0*FF, rowA1 = (size_t)gr1*FF;

    float sacc[8][4];
#pragma unroll
    for (int nt = 0; nt < 8; nt++)
#pragma unroll
        for (int e = 0; e < 4; e++) sacc[nt][e] = 0.f;

    uint32_t a0[4], a1[4];
    {
        int c0 = t4*2;
        a0[0] = *(const uint32_t*)(Ab + rowA0 + c0);
        a0[1] = *(const uint32_t*)(Ab + rowA1 + c0);
        a0[2] = *(const uint32_t*)(Ab + rowA0 + c0 + 8);
        a0[3] = *(const uint32_t*)(Ab + rowA1 + c0 + 8);
        c0 += 16;
        a1[0] = *(const uint32_t*)(Ab + rowA0 + c0);
        a1[1] = *(const uint32_t*)(Ab + rowA1 + c0);
        a1[2] = *(const uint32_t*)(Ab + rowA0 + c0 + 8);
        a1[3] = *(const uint32_t*)(Ab + rowA1 + c0 + 8);
    }

#pragma unroll
    for (int kt = 0; kt < 16; kt++) {
        int c0 = kt*16 + t4*2;
#pragma unroll
        for (int nt = 0; nt < 8; nt++) {
            int off = (nt*8 + g4)*PJ_WPITCH + c0*2;
            uint32_t bh2[2];
            bh2[0] = *(const uint32_t*)(sWh + off);
            bh2[1] = *(const uint32_t*)(sWh + off + 16);
            mma16816(sacc[nt], a0, bh2);
        }
#pragma unroll
        for (int e = 0; e < 4; e++) a0[e] = a1[e];
        if (kt < 14) {
            int cn = (kt + 2)*16 + t4*2;
            a1[0] = *(const uint32_t*)(Ab + rowA0 + cn);
            a1[1] = *(const uint32_t*)(Ab + rowA1 + cn);
            a1[2] = *(const uint32_t*)(Ab + rowA0 + cn + 8);
            a1[3] = *(const uint32_t*)(Ab + rowA1 + cn + 8);
        }
    }

    if (mode) {
        // ---- transpose vh via smem -> g_vT [bh][d][j] bf16
        __syncthreads();
#pragma unroll
        for (int nt = 0; nt < 8; nt++) {
            int d0 = nt*8 + t4*2;
            vtr[d0*132 + r0]         = sacc[nt][0];
            vtr[(d0+1)*132 + r0]     = sacc[nt][1];
            vtr[d0*132 + r0 + 8]     = sacc[nt][2];
            vtr[(d0+1)*132 + r0 + 8] = sacc[nt][3];
        }
        __syncthreads();
        __nv_bfloat16* vTh = (__nv_bfloat16*)g_vT_h4;
        for (int idx = tid; idx < 4096; idx += 256) {
            int d = idx >> 6, jp = idx & 63;
            int gj = m0 + 2*jp;
            int b = gj / LL, p = gj - b*LL;   // pairs never cross batch (500 even)
            size_t a = ((size_t)((b*HH + h)*DKK + d))*LPAD + p;
            *(uint32_t*)(vTh + a) = pack_hi2(vtr[d*132 + 2*jp], vtr[d*132 + 2*jp + 1]);
        }
        return;
    }

    // ---- hand-off: qh C-frags -> A-frags
    uint32_t ph[4][4];
#pragma unroll
    for (int nt = 0; nt < 8; nt++) {
        int kt = nt >> 1, i0 = (nt & 1) * 2;
        ph[kt][i0]     = pack_hi2(sacc[nt][0], sacc[nt][1]);
        ph[kt][i0 + 1] = pack_hi2(sacc[nt][2], sacc[nt][3]);
    }

    float s2[8][4];
#pragma unroll
    for (int nt = 0; nt < 8; nt++) {
        int col = nt*8 + t4*2;
        s2[nt][0] = s2[nt][2] = b1s[col];
        s2[nt][1] = s2[nt][3] = b1s[col + 1];
    }
#pragma unroll
    for (int kt = 0; kt < 4; kt++) {
#pragma unroll
        for (int nt = 0; nt < 8; nt++) {
            int off = (nt*8 + g4)*144 + (kt*16 + t4*2)*2;
            uint32_t bh2[2];
            bh2[0] = *(const uint32_t*)(sW1h + off);
            bh2[1] = *(const uint32_t*)(sW1h + off + 16);
            mma16816(s2[nt], ph[kt], bh2);
        }
    }

    // relu + store g_wt (bf16)
    __nv_bfloat16* wth = (__nv_bfloat16*)g_wt_h4;
    int b0_ = gr0 / LL, l0_ = gr0 - b0_*LL;
    int b1_ = gr1 / LL, l1_ = gr1 - b1_*LL;
    size_t base0 = ((size_t)((b0_*HH + h)*LL + l0_))*DKK;
    size_t base1 = ((size_t)((b1_*HH + h)*LL + l1_))*DKK;
#pragma unroll
    for (int nt = 0; nt < 8; nt++) {
        int d = nt*8 + t4*2;
        *(uint32_t*)(wth + base0 + d) =
            pack_hi2(fmaxf(s2[nt][0], 0.f), fmaxf(s2[nt][1], 0.f));
        *(uint32_t*)(wth + base1 + d) =
            pack_hi2(fmaxf(s2[nt][2], 0.f), fmaxf(s2[nt][3], 0.f));
    }
}

// ---------------------------------------------------------------------------
// Kernel 2: attention (round-12 version). grid (4, H, B), 256 thr.
// ---------------------------------------------------------------------------
#define SPITCH 144
#define ATILE (64*SPITCH)   // 9216

__global__ void __launch_bounds__(256)
k_attn_mma(const float* __restrict__ b2)
{
    __shared__ float b2all[512];
    __shared__ __align__(16) char sW2[2][ATILE];
    __shared__ __align__(16) char sV [2][ATILE];

    const int tid  = threadIdx.x;
    const int lane = tid & 31, wid = tid >> 5;
    const int g4 = lane >> 2, t4 = lane & 3;
    const int l0 = blockIdx.x * 128;
    const int h  = blockIdx.y, b = blockIdx.z;
    const int bh = b*HH + h;
    const int r0 = l0 + wid*16 + g4;

    const uint32_t sW2a = (uint32_t)__cvta_generic_to_shared(sW2);
    const uint32_t sVa  = (uint32_t)__cvta_generic_to_shared(sV);

#pragma unroll
    for (int it = 0; it < 2; it++) {
        int i = tid + it*256;
        b2all[i] = (i < LL) ? b2[i] : 0.f;
    }

    const __nv_bfloat16* wth = (const __nv_bfloat16*)g_wt_h4;
    uint32_t aWh[4][4];
    {
        const bool v0 = (r0 < LL), v1 = (r0 + 8 < LL);
        size_t base0 = (size_t)(bh*LL + r0)*DKK;
        size_t base1 = (size_t)(bh*LL + r0 + 8)*DKK;
#pragma unroll
        for (int kt = 0; kt < 4; kt++) {
            int c0 = kt*16 + t4*2, c8 = c0 + 8;
            aWh[kt][0] = v0 ? *(const uint32_t*)(wth + base0 + c0) : 0u;
            aWh[kt][1] = v1 ? *(const uint32_t*)(wth + base1 + c0) : 0u;
            aWh[kt][2] = v0 ? *(const uint32_t*)(wth + base0 + c8) : 0u;
            aWh[kt][3] = v1 ? *(const uint32_t*)(wth + base1 + c8) : 0u;
        }
    }

    float oacc[8][4];
#pragma unroll
    for (int nt = 0; nt < 8; nt++)
#pragma unroll
        for (int e = 0; e < 4; e++) oacc[nt][e] = 0.f;
    float dp0 = 0.f, dp1 = 0.f;

#pragma unroll
    for (int it = 0; it < 2; it++) {
        int idx = tid + it*256;
        int rr = idx >> 3, gg = idx & 7;
        cpa16(sW2a + rr*SPITCH + gg*16, &g_w2T_h4[(size_t)rr*8 + gg]);
        cpa16(sVa  + rr*SPITCH + gg*16,
              &g_vT_h4[(size_t)(bh*DKK + rr)*(LPAD/8) + gg]);
    }
    CPA_COMMIT();

    for (int c = 0; c < 8; c++) {
        const int j0 = c * 64;
        const int buf = c & 1;
        CPA_WAIT0();
        __syncthreads();
        if (c < 7) {
            const int jn = (c + 1) * 64;
            const uint32_t dW2 = sW2a + (buf ^ 1)*ATILE;
            const uint32_t dV  = sVa  + (buf ^ 1)*ATILE;
#pragma unroll
            for (int it = 0; it < 2; it++) {
                int idx = tid + it*256;
                int rr = idx >> 3, gg = idx & 7;
                cpa16(dW2 + rr*SPITCH + gg*16, &g_w2T_h4[(size_t)(jn + rr)*8 + gg]);
                cpa16(dV  + rr*SPITCH + gg*16,
                      &g_vT_h4[(size_t)(bh*DKK + rr)*(LPAD/8) + (jn >> 3) + gg]);
            }
            CPA_COMMIT();
        }

        const char* w2b = sW2[buf];
        const char* vb  = sV[buf];

        float sacc[8][4];
#pragma unroll
        for (int nt = 0; nt < 8; nt++)
#pragma unroll
            for (int e = 0; e < 4; e++) sacc[nt][e] = 0.f;

#pragma unroll
        for (int kt = 0; kt < 4; kt++) {
#pragma unroll
            for (int nt = 0; nt < 8; nt++) {
                int off = (nt*8 + g4)*SPITCH + (kt*16 + t4*2)*2;
                uint32_t bh2[2];
                bh2[0] = *(const uint32_t*)(w2b + off);
                bh2[1] = *(const uint32_t*)(w2b + off + 16);
                mma16816(sacc[nt], aWh[kt], bh2);
            }
        }

        uint32_t phA[4][4];
#pragma unroll
        for (int nt = 0; nt < 8; nt++) {
            int jl = nt*8 + t4*2;
            int jg = j0 + jl;
            float bb0 = b2all[jg], bb1 = b2all[jg + 1];
            float p0 = (jg     < LL) ? __expf(sacc[nt][0] + bb0) : 0.f;
            float p1 = (jg + 1 < LL) ? __expf(sacc[nt][1] + bb1) : 0.f;
            float p2 = (jg     < LL) ? __expf(sacc[nt][2] + bb0) : 0.f;
            float p3 = (jg + 1 < LL) ? __expf(sacc[nt][3] + bb1) : 0.f;
            dp0 += p0 + p1;
            dp1 += p2 + p3;
            int kt = nt >> 1, i0 = (nt & 1) * 2;
            phA[kt][i0]     = pack_hi2(p0, p1);
            phA[kt][i0 + 1] = pack_hi2(p2, p3);
        }

#pragma unroll
        for (int kt = 0; kt < 4; kt++) {
#pragma unroll
            for (int nt = 0; nt < 8; nt++) {
                int off = (nt*8 + g4)*SPITCH + (kt*16 + t4*2)*2;
                uint32_t bvh[2];
                bvh[0] = *(const uint32_t*)(vb + off);
                bvh[1] = *(const uint32_t*)(vb + off + 16);
                mma16816(oacc[nt], phA[kt], bvh);
            }
        }
    }

    dp0 += __shfl_xor_sync(0xffffffffu, dp0, 1);
    dp0 += __shfl_xor_sync(0xffffffffu, dp0, 2);
    dp1 += __shfl_xor_sync(0xffffffffu, dp1, 1);
    dp1 += __shfl_xor_sync(0xffffffffu, dp1, 2);
    float inv0 = 1.f / dp0, inv1 = 1.f / dp1;

    if (r0 < LL) {
        __nv_bfloat16* dst = g_ctxb + ((size_t)(b*LL + r0))*FF + h*DKK + t4*2;
#pragma unroll
        for (int nt = 0; nt < 8; nt++)
            *(uint32_t*)(dst + nt*8) = pack_hi2(oacc[nt][0]*inv0, oacc[nt][1]*inv0);
    }
    if (r0 + 8 < LL) {
        __nv_bfloat16* dst = g_ctxb + ((size_t)(b*LL + r0 + 8))*FF + h*DKK + t4*2;
#pragma unroll
        for (int nt = 0; nt < 8; nt++)
            *(uint32_t*)(dst + nt*8) = pack_hi2(oacc[nt][2]*inv1, oacc[nt][3]*inv1);
    }
}

// ---------------------------------------------------------------------------
// Kernel 3: out = LN(ctx @ fcwT^T + q). grid 500 (M=64/CTA), 256 thr.
// fcw AND ctx tiles staged via cp.async (double-buffered, one commit group).
// ---------------------------------------------------------------------------
#define FTILE (256*144)          // 36864
#define CTILE (64*144)           // 9216
#define FN_CTXOFF (2*FTILE)      // 73728
#define FN_SMEM (FN_CTXOFF + 2*CTILE)   // 92160

__global__ void __launch_bounds__(256)
k_final_mma(const float* __restrict__ qin, const float* __restrict__ lng,
            const float* __restrict__ lnb, float* __restrict__ out)
{
    extern __shared__ char smem[];
    __shared__ float red_s[64][2], red_q[64][2];
    const uint32_t sFa = (uint32_t)__cvta_generic_to_shared(smem);
    const uint32_t sCa = sFa + FN_CTXOFF;

    const int tid  = threadIdx.x;
    const int lane = tid & 31, wid = tid >> 5;
    const int g4 = lane >> 2, t4 = lane & 3;
    const int half = wid >> 2, wrow = wid & 3;
    const int ncol0 = half * 128;
    const int m0 = blockIdx.x * 64;
    const int r0 = wrow*16 + g4;
    const int gr0 = m0 + r0, gr1 = gr0 + 8;
    const __nv_bfloat16* ctxb = g_ctxb;

    float sacc[16][4];
#pragma unroll
    for (int nt = 0; nt < 16; nt++)
#pragma unroll
        for (int e = 0; e < 4; e++) sacc[nt][e] = 0.f;

    // stage kc=0: fcw (512 granules) + ctx (512 granules)
#pragma unroll
    for (int it = 0; it < 8; it++) {
        int idx = tid + it*256;
        int row = idx >> 3, gq = idx & 7;
        cpa16(sFa + row*144 + gq*16, &g_fcwT4h[row*32 + gq]);
    }
#pragma unroll
    for (int it = 0; it < 2; it++) {
        int idx = tid + it*256;
        int rr = idx >> 3, gg = idx & 7;
        cpa16(sCa + rr*144 + gg*16, ctxb + (size_t)(m0 + rr)*FF + gg*8);
    }
    CPA_COMMIT();

    for (int kc = 0; kc < 4; kc++) {
        const int buf = kc & 1;
        CPA_WAIT0();
        __syncthreads();
        if (kc < 3) {
            const uint32_t dF = sFa + (buf ^ 1)*FTILE;
            const uint32_t dC = sCa + (buf ^ 1)*CTILE;
#pragma unroll
            for (int it = 0; it < 8; it++) {
                int idx = tid + it*256;
                int row = idx >> 3, gq = idx & 7;
                cpa16(dF + row*144 + gq*16, &g_fcwT4h[row*32 + (kc+1)*8 + gq]);
            }
#pragma unroll
            for (int it = 0; it < 2; it++) {
                int idx = tid + it*256;
                int rr = idx >> 3, gg = idx & 7;
                cpa16(dC + rr*144 + gg*16,
                      ctxb + (size_t)(m0 + rr)*FF + (kc+1)*64 + gg*8);
            }
            CPA_COMMIT();
        }
        const char* sFh = smem + buf*FTILE;
        const char* sCh = smem + FN_CTXOFF + buf*CTILE;

#pragma unroll
        for (int kt = 0; kt < 4; kt++) {
            int cl = (kt*16 + t4*2)*2;     // byte offset within ctx tile row
            uint32_t ah[4];
            ah[0] = *(const uint32_t*)(sCh + r0*144 + cl);
            ah[1] = *(const uint32_t*)(sCh + (r0 + 8)*144 + cl);
            ah[2] = *(const uint32_t*)(sCh + r0*144 + cl + 16);
            ah[3] = *(const uint32_t*)(sCh + (r0 + 8)*144 + cl + 16);
            int koff = (kt*16 + t4*2)*2;
#pragma unroll
            for (int nt = 0; nt < 16; nt++) {
                int off = (ncol0 + nt*8 + g4)*144 + koff;
                uint32_t bh2[2];
                bh2[0] = *(const uint32_t*)(sFh + off);
                bh2[1] = *(const uint32_t*)(sFh + off + 16);
                mma16816(sacc[nt], ah, bh2);
            }
        }
    }

    float sum0 = 0.f, sq0 = 0.f, sum1 = 0.f, sq1 = 0.f;
#pragma unroll
    for (int nt = 0; nt < 16; nt++) {
        int col = ncol0 + nt*8 + t4*2;
        float2 q0 = *(const float2*)(qin + (size_t)gr0*FF + col);
        float2 q1 = *(const float2*)(qin + (size_t)gr1*FF + col);
        sacc[nt][0] += q0.x; sacc[nt][1] += q0.y;
        sacc[nt][2] += q1.x; sacc[nt][3] += q1.y;
        sum0 += sacc[nt][0] + sacc[nt][1];
        sq0  += sacc[nt][0]*sacc[nt][0] + sacc[nt][1]*sacc[nt][1];
        sum1 += sacc[nt][2] + sacc[nt][3];
        sq1  += sacc[nt][2]*sacc[nt][2] + sacc[nt][3]*sacc[nt][3];
    }
    sum0 += __shfl_xor_sync(0xffffffffu, sum0, 1);
    sum0 += __shfl_xor_sync(0xffffffffu, sum0, 2);
    sq0  += __shfl_xor_sync(0xffffffffu, sq0, 1);
    sq0  += __shfl_xor_sync(0xffffffffu, sq0, 2);
    sum1 += __shfl_xor_sync(0xffffffffu, sum1, 1);
    sum1 += __shfl_xor_sync(0xffffffffu, sum1, 2);
    sq1  += __shfl_xor_sync(0xffffffffu, sq1, 1);
    sq1  += __shfl_xor_sync(0xffffffffu, sq1, 2);

    __syncthreads();
    if (t4 == 0) {
        red_s[r0][half] = sum0;     red_q[r0][half] = sq0;
        red_s[r0 + 8][half] = sum1; red_q[r0 + 8][half] = sq1;
    }
    __syncthreads();

    float s0 = red_s[r0][0] + red_s[r0][1];
    float qq0 = red_q[r0][0] + red_q[r0][1];
    float s1 = red_s[r0 + 8][0] + red_s[r0 + 8][1];
    float qq1 = red_q[r0 + 8][0] + red_q[r0 + 8][1];

    float mu0 = s0 * (1.f/256.f);
    float mu1 = s1 * (1.f/256.f);
    float rstd0 = rsqrtf(qq0 * (1.f/256.f) - mu0*mu0 + 1e-6f);
    float rstd1 = rsqrtf(qq1 * (1.f/256.f) - mu1*mu1 + 1e-6f);

#pragma unroll
    for (int nt = 0; nt < 16; nt++) {
        int col = ncol0 + nt*8 + t4*2;
        float2 g = *(const float2*)(lng + col);
        float2 bt = *(const float2*)(lnb + col);
        float2 o0, o1;
        o0.x = (sacc[nt][0] - mu0)*rstd0*g.x + bt.x;
        o0.y = (sacc[nt][1] - mu0)*rstd0*g.y + bt.y;
        o1.x = (sacc[nt][2] - mu1)*rstd1*g.x + bt.x;
        o1.y = (sacc[nt][3] - mu1)*rstd1*g.y + bt.y;
        *(float2*)(out + (size_t)gr0*FF + col) = o0;
        *(float2*)(out + (size_t)gr1*FF + col) = o1;
    }
}

// ---------------------------------------------------------------------------
extern "C" void kernel_launch(void* const* d_in, const int* in_sizes, int n_in,
                              void* d_out, int out_size)
{
    const float* q    = (const float*)d_in[0];
    const float* v    = (const float*)d_in[2];   // d_in[1] (k) unused by model
    const float* w_qs = (const float*)d_in[3];
    const float* w_vs = (const float*)d_in[4];
    const float* w1   = (const float*)d_in[5];
    const float* b1   = (const float*)d_in[6];
    const float* w2   = (const float*)d_in[7];
    const float* b2   = (const float*)d_in[8];
    const float* fcw  = (const float*)d_in[9];
    const float* lng  = (const float*)d_in[10];
    const float* lnb  = (const float*)d_in[11];
    float* out = (float*)d_out;

    cudaFuncSetAttribute(k_proj_mma,  cudaFuncAttributeMaxDynamicSharedMemorySize, PJ_SMEM);
    cudaFuncSetAttribute(k_final_mma, cudaFuncAttributeMaxDynamicSharedMemorySize, FN_SMEM);

    k_prep_all <<<4912, 256>>>(w2, w_qs, w_vs, fcw, w1, q, v);
    k_proj_mma <<<dim3(250, HH, 2), 256, PJ_SMEM>>>(b1);
    k_attn_mma <<<dim3(4, HH, BB),  256>>>(b2);
    k_final_mma<<<500,              256, FN_SMEM>>>(q, lng, lnb, out);
}